// round 7
// baseline (speedup 1.0000x reference)
#include <cuda_runtime.h>
#include <cuda_bf16.h>
#include <cstdint>

// B=8, N=2048, FEAT=16, pos = feats [0,2), radius = 0.25.
// Output [B, N, N] fp32 mask = 128 MiB compulsory stores.
// Single kernel, smem-staged positions: main loop does ZERO global reads,
// leaving the whole L2/HBM path to the store drain.
static constexpr int N_     = 2048;
static constexpr int BATCH_ = 8;
static constexpr int R_ROWS = 16;          // rows per block (register-reuse tile)
static constexpr float R2   = 0.0625f;     // 0.25^2

__device__ __forceinline__ int read_idx_arr(const int* __restrict__ a32, int b)
{
    // Handles both int32 and int64(small values) materialization of T/taus.
    const bool is64 = (a32[1] == 0) && (a32[0] != 0);
    return is64 ? a32[2 * b] : a32[b];
}

__global__ void __launch_bounds__(512, 3)
radius_edge_kernel(const float* __restrict__ nodes,
                   const int* __restrict__ T_arr,
                   const int* __restrict__ tau_arr,
                   float4* __restrict__ out)
{
    __shared__ float2 s_pos[N_];               // 16KB: this batch's positions

    // grid = B * (N / R_ROWS) = 1024 blocks x 512 threads
    const int b  = blockIdx.x >> 7;            // /128
    const int i0 = (blockIdx.x & 127) * R_ROWS;
    const int t  = threadIdx.x;                // one float4 column-group each

    const int Tlo = read_idx_arr(T_arr, b);
    const int Thi = Tlo + read_idx_arr(tau_arr, b);  // active cols [Tlo, Thi)

    const int j0 = 4 * t;
    const float* __restrict__ nb = nodes + (size_t)b * N_ * 16;

    // Stage: each thread reads its own 4 column positions (the only global
    // reads in the kernel), keeps them in registers, deposits into smem for
    // the per-row broadcast.
    float px[4], py[4];
    #pragma unroll
    for (int k = 0; k < 4; k++) {
        const float2 p = *(const float2*)(nb + (size_t)(j0 + k) * 16);
        px[k] = p.x;
        py[k] = p.y;
        s_pos[j0 + k] = p;
    }
    __syncthreads();

    // Loop-invariant column-window mask.
    bool w[4];
    #pragma unroll
    for (int k = 0; k < 4; k++)
        w[k] = (j0 + k >= Tlo) && (j0 + k < Thi);

    float4* orow = out + ((size_t)b * N_ + i0) * (N_ / 4) + t;

    #pragma unroll 4
    for (int r = 0; r < R_ROWS; r++) {
        const int i = i0 + r;
        const float2 pi = s_pos[i];   // uniform -> conflict-free smem broadcast

        float4 v;
        #pragma unroll
        for (int k = 0; k < 4; k++) {
            const float dx = pi.x - px[k];
            const float dy = pi.y - py[k];
            const bool  c  = w[k] & (i < j0 + k) & (fmaf(dx, dx, dy * dy) < R2);
            (&v.x)[k] = c ? 1.0f : 0.0f;
        }
        orow[(size_t)r * (N_ / 4)] = v;   // coalesced STG.128, 8KB per block-row
    }
}

extern "C" void kernel_launch(void* const* d_in, const int* in_sizes, int n_in,
                              void* d_out, int out_size)
{
    const float* nodes   = (const float*)d_in[0];
    const int*   T_arr   = (const int*)d_in[1];
    const int*   tau_arr = (const int*)d_in[2];
    // d_in[3] = B scalar, unused (compile-time constants)

    const int blocks = BATCH_ * (N_ / R_ROWS);   // 1024
    radius_edge_kernel<<<blocks, 512>>>(nodes, T_arr, tau_arr, (float4*)d_out);
}

// round 9
// speedup vs baseline: 1.0462x; 1.0462x over previous
#include <cuda_runtime.h>
#include <cuda_bf16.h>
#include <cstdint>

// B=8, N=2048, FEAT=16, pos = feats [0,2), radius = 0.25.
// Output [B, N, N] fp32 mask = 128 MiB compulsory stores.
// Single kernel, 512 blocks x 2 row-tiles each: column positions read once per
// block (strided) and reused across 32 rows -> halves prologue L2 traffic vs
// one-tile-per-block, keeps single-launch (no second kernel / graph node).
static constexpr int N_     = 2048;
static constexpr int BATCH_ = 8;
static constexpr int R_ROWS = 16;          // rows per tile
static constexpr int TILES_PER_BLOCK = 2;  // 32 rows per block
static constexpr float R2   = 0.0625f;     // 0.25^2

__device__ __forceinline__ int read_idx_arr(const int* __restrict__ a32, int b)
{
    // Handles both int32 and int64(small values) materialization of T/taus.
    const bool is64 = (a32[1] == 0) && (a32[0] != 0);
    return is64 ? a32[2 * b] : a32[b];
}

__global__ void __launch_bounds__(512, 3)
radius_edge_kernel(const float* __restrict__ nodes,
                   const int* __restrict__ T_arr,
                   const int* __restrict__ tau_arr,
                   float4* __restrict__ out)
{
    // grid = 512: 64 blocks per batch, each covering 2 tiles 1024 rows apart.
    const int b = blockIdx.x >> 6;             // /64
    const int q = blockIdx.x & 63;             // tile pair index within batch
    const int t = threadIdx.x;                 // one float4 column-group each

    const int Tlo = read_idx_arr(T_arr, b);
    const int Thi = Tlo + read_idx_arr(tau_arr, b);  // active cols [Tlo, Thi)

    const int j0 = 4 * t;
    const float* __restrict__ nb = nodes + (size_t)b * N_ * 16;

    // Read this thread's 4 column positions ONCE, reuse across 32 rows.
    float px[4], py[4];
    #pragma unroll
    for (int k = 0; k < 4; k++) {
        const float2 p = __ldg((const float2*)(nb + (size_t)(j0 + k) * 16));
        px[k] = p.x;
        py[k] = p.y;
    }

    // Loop-invariant column-window mask.
    bool w[4];
    #pragma unroll
    for (int k = 0; k < 4; k++)
        w[k] = (j0 + k >= Tlo) && (j0 + k < Thi);

    #pragma unroll
    for (int tile = 0; tile < TILES_PER_BLOCK; tile++) {
        const int i0 = (q + tile * 64) * R_ROWS;   // rows [i0, i0+16)
        float4* orow = out + ((size_t)b * N_ + i0) * (N_ / 4) + t;

        #pragma unroll 4
        for (int r = 0; r < R_ROWS; r++) {
            const int i = i0 + r;
            // Uniform broadcast load: one sector, L1-hit after first touch.
            const float2 pi = __ldg((const float2*)(nb + (size_t)i * 16));

            float4 v;
            #pragma unroll
            for (int k = 0; k < 4; k++) {
                const float dx = pi.x - px[k];
                const float dy = pi.y - py[k];
                const bool  c  = w[k] & (i < j0 + k) & (fmaf(dx, dx, dy * dy) < R2);
                (&v.x)[k] = c ? 1.0f : 0.0f;
            }
            orow[(size_t)r * (N_ / 4)] = v;   // coalesced STG.128
        }
    }
}

extern "C" void kernel_launch(void* const* d_in, const int* in_sizes, int n_in,
                              void* d_out, int out_size)
{
    const float* nodes   = (const float*)d_in[0];
    const int*   T_arr   = (const int*)d_in[1];
    const int*   tau_arr = (const int*)d_in[2];
    // d_in[3] = B scalar, unused (compile-time constants)

    const int blocks = BATCH_ * (N_ / R_ROWS) / TILES_PER_BLOCK;   // 512
    radius_edge_kernel<<<blocks, 512>>>(nodes, T_arr, tau_arr, (float4*)d_out);
}

// round 12
// speedup vs baseline: 1.0858x; 1.0379x over previous
#include <cuda_runtime.h>
#include <cuda_bf16.h>
#include <cstdint>

// B=8, N=2048, FEAT=16, pos = feats [0,2), radius = 0.25.
// Output [B, N, N] fp32 mask = 128 MiB compulsory stores (~5.6 TB/s wall).
// Two-kernel structure (empirically 4-5us faster than fused/strided reads):
//   1) compact: strided nodes -> dense g_pos (128 KB), once.
//   2) main: dense reads only; 32 rows/block to maximize register reuse and
//      minimize read traffic colliding with the store drain.
static constexpr int N_     = 2048;
static constexpr int BATCH_ = 8;
static constexpr int R_ROWS = 32;          // rows per block
static constexpr float R2   = 0.0625f;     // 0.25^2

__device__ __align__(16) float2 g_pos[BATCH_][N_];

__device__ __forceinline__ int read_idx_arr(const int* __restrict__ a32, int b)
{
    // Handles both int32 and int64(small values) materialization of T/taus.
    const bool is64 = (a32[1] == 0) && (a32[0] != 0);
    return is64 ? a32[2 * b] : a32[b];
}

__global__ void __launch_bounds__(128)
compact_kernel(const float* __restrict__ nodes)
{
    const int node = blockIdx.x * 128 + threadIdx.x;   // 128 blocks x 128 = 16384
    const float2 p = *(const float2*)(nodes + (size_t)node * 16);
    reinterpret_cast<float2*>(g_pos)[node] = p;        // coalesced 8B store
}

__global__ void __launch_bounds__(256)
radius_edge_kernel(const int* __restrict__ T_arr,
                   const int* __restrict__ tau_arr,
                   float4* __restrict__ out)
{
    // grid = B * (N / R_ROWS) = 8 * 64 = 512 blocks x 256 threads.
    const int b  = blockIdx.x >> 6;            // /64
    const int i0 = (blockIdx.x & 63) * R_ROWS;
    const int t  = threadIdx.x;                // two float4 column-groups each

    const int Tlo = read_idx_arr(T_arr, b);
    const int Thi = Tlo + read_idx_arr(tau_arr, b);  // active cols [Tlo, Thi)

    const int j0a = 4 * t;
    const int j0b = 4 * (t + 256);

    // Load the 8 column positions ONCE (4 coalesced LDG.128 from dense g_pos),
    // reuse across all 32 rows.
    const float4* pbase = reinterpret_cast<const float4*>(&g_pos[b][0]);
    const float4 ra0 = pbase[2 * t];
    const float4 ra1 = pbase[2 * t + 1];
    const float4 rb0 = pbase[2 * (t + 256)];
    const float4 rb1 = pbase[2 * (t + 256) + 1];

    const float pax[4] = {ra0.x, ra0.z, ra1.x, ra1.z};
    const float pay[4] = {ra0.y, ra0.w, ra1.y, ra1.w};
    const float pbx[4] = {rb0.x, rb0.z, rb1.x, rb1.z};
    const float pby[4] = {rb0.y, rb0.w, rb1.y, rb1.w};

    // Loop-invariant window masks.
    bool wa[4], wb[4];
    #pragma unroll
    for (int k = 0; k < 4; k++) {
        wa[k] = (j0a + k >= Tlo) && (j0a + k < Thi);
        wb[k] = (j0b + k >= Tlo) && (j0b + k < Thi);
    }

    float4* orow = out + ((size_t)b * N_ + i0) * (N_ / 4);

    #pragma unroll 4
    for (int r = 0; r < R_ROWS; r++) {
        const int i = i0 + r;
        const float2 pi = g_pos[b][i];   // uniform -> broadcast load (L1 hit)

        float4 va, vb;
        #pragma unroll
        for (int k = 0; k < 4; k++) {
            float dx = pi.x - pax[k];
            float dy = pi.y - pay[k];
            bool  c  = wa[k] & (i < j0a + k) & (fmaf(dx, dx, dy * dy) < R2);
            (&va.x)[k] = c ? 1.0f : 0.0f;

            dx = pi.x - pbx[k];
            dy = pi.y - pby[k];
            c  = wb[k] & (i < j0b + k) & (fmaf(dx, dx, dy * dy) < R2);
            (&vb.x)[k] = c ? 1.0f : 0.0f;
        }

        orow[(size_t)r * (N_ / 4) + t]       = va;   // coalesced STG.128
        orow[(size_t)r * (N_ / 4) + t + 256] = vb;
    }
}

extern "C" void kernel_launch(void* const* d_in, const int* in_sizes, int n_in,
                              void* d_out, int out_size)
{
    const float* nodes   = (const float*)d_in[0];
    const int*   T_arr   = (const int*)d_in[1];
    const int*   tau_arr = (const int*)d_in[2];
    // d_in[3] = B scalar, unused (compile-time constants)

    compact_kernel<<<128, 128>>>(nodes);         // 16384 nodes, 1 thread each

    const int blocks = BATCH_ * (N_ / R_ROWS);   // 512
    radius_edge_kernel<<<blocks, 256>>>(T_arr, tau_arr, (float4*)d_out);
}